// round 13
// baseline (speedup 1.0000x reference)
#include <cuda_runtime.h>
#include <cuda_fp16.h>
#include <cstdint>

// Problem constants
#define Bb 8
#define Ss 2048
#define Dd 512
#define Qq 8
#define Kk 1024
#define Mm (Bb * Ss)   // 16384 tokens
#define MARGIN 8.0f

// Scratch (no cudaMalloc allowed)
__device__ float   g_residual[Mm * Dd];   // 32 MB fp32 residual
__device__ __half  g_res16[Mm * Dd];      // 16 MB fp16 residual
__device__ __half  g_cb16[Qq * Kk * Dd];  //  8 MB fp16 codebooks
__device__ __half  g_dist[Mm * Kk];       // 32 MB approx distances (fp16)
__device__ float   g_bmin[8 * Mm];        // 512 KB per-(nblock, token) min
__device__ float   g_c2[Qq * Kk];
__device__ float   g_loss[Qq];

// ---------------------------------------------------------------------------
// helpers
// ---------------------------------------------------------------------------
__device__ __forceinline__ uint32_t smem_u32(const void* p) {
    uint32_t a;
    asm("{ .reg .u64 t; cvta.to.shared.u64 t, %1; cvt.u32.u64 %0, t; }"
        : "=r"(a) : "l"(p));
    return a;
}
__device__ __forceinline__ void cp16(uint32_t sa, const void* g) {
    asm volatile("cp.async.cg.shared.global [%0], [%1], 16;"
                 :: "r"(sa), "l"(g) : "memory");
}
__device__ __forceinline__ void cp_commit() {
    asm volatile("cp.async.commit_group;" ::: "memory");
}
__device__ __forceinline__ void cp_wait0() {
    asm volatile("cp.async.wait_group 0;" ::: "memory");
}
__device__ __forceinline__ void ldsm4(uint32_t* r, uint32_t addr) {
    asm volatile("ldmatrix.sync.aligned.m8n8.x4.shared.b16 {%0,%1,%2,%3}, [%4];"
                 : "=r"(r[0]), "=r"(r[1]), "=r"(r[2]), "=r"(r[3])
                 : "r"(addr));
}
// fp16 inputs, fp16 accumulators (2 x b32 regs hold 4 halves)
__device__ __forceinline__ void mma_f16acc(uint32_t* c, const uint32_t* a,
                                           uint32_t b0, uint32_t b1) {
    asm volatile(
        "mma.sync.aligned.m16n8k16.row.col.f16.f16.f16.f16 "
        "{%0,%1}, {%2,%3,%4,%5}, {%6,%7}, {%0,%1};"
        : "+r"(c[0]), "+r"(c[1])
        : "r"(a[0]), "r"(a[1]), "r"(a[2]), "r"(a[3]), "r"(b0), "r"(b1));
}
// order-preserving float <-> uint for atomicMin
__device__ __forceinline__ uint32_t ordkey(float f) {
    uint32_t u = __float_as_uint(f);
    return (u & 0x80000000u) ? ~u : (u | 0x80000000u);
}
__device__ __forceinline__ float orddec(uint32_t k) {
    return (k & 0x80000000u) ? __uint_as_float(k ^ 0x80000000u)
                             : __uint_as_float(~k);
}

// ---------------------------------------------------------------------------
// init: residual=x (fp32), res16=fp16(x)
// ---------------------------------------------------------------------------
__global__ void init_kernel(const float4* __restrict__ x,
                            float4* __restrict__ residual,
                            __half2* __restrict__ res16, int n4)
{
    int i = blockIdx.x * 256 + threadIdx.x;
    if (i < n4) {
        float4 v = x[i];
        residual[i] = v;
        res16[2 * i]     = __floats2half2_rn(v.x, v.y);
        res16[2 * i + 1] = __floats2half2_rn(v.z, v.w);
    }
}

// fp32 -> fp16 codebook convert
__global__ void conv_kernel(const float4* __restrict__ in,
                            __half2* __restrict__ out, int n4)
{
    int i = blockIdx.x * 256 + threadIdx.x;
    if (i < n4) {
        float4 v = in[i];
        out[2 * i]     = __floats2half2_rn(v.x, v.y);
        out[2 * i + 1] = __floats2half2_rn(v.z, v.w);
    }
}

// ---------------------------------------------------------------------------
// c2[q][k] = ||codebook[q][k]||^2  — one warp per row (fp32 exact)
// ---------------------------------------------------------------------------
__global__ void c2_kernel(const float* __restrict__ codebooks, float* __restrict__ c2)
{
    int row  = blockIdx.x * 8 + (threadIdx.x >> 5);
    int lane = threadIdx.x & 31;
    const float4* p = (const float4*)(codebooks + (size_t)row * Dd);
    float s = 0.0f;
    #pragma unroll 4
    for (int i = lane; i < Dd / 4; i += 32) {
        float4 v = p[i];
        s += v.x * v.x + v.y * v.y + v.z * v.z + v.w * v.w;
    }
    #pragma unroll
    for (int off = 16; off; off >>= 1) s += __shfl_down_sync(0xffffffffu, s, off);
    if (lane == 0) c2[row] = s;
}

// ---------------------------------------------------------------------------
// fp16 mma.sync GEMM (fp16 acc) -> approx distances (fp16) + per-token
// block-min for this CTA's 128 codes.
// CTA 128x128, BK=64, 8 warps of 32x64, double-buffered cp.async, one sync
// per k-tile, fragment loads software-pipelined across the s-loop.
// ---------------------------------------------------------------------------
#define GEMM_SMEM (65536 + 512)   // 2 bufs * (A 16KB + B 16KB) + rmin[128]

__global__ __launch_bounds__(256, 2)
void gemm_dist_kernel(const __half* __restrict__ A16,
                      const __half* __restrict__ B16,
                      const float* __restrict__ c2,
                      __half* __restrict__ dist,
                      float* __restrict__ bminO)
{
    extern __shared__ char sm[];
    const uint32_t smb   = smem_u32(sm);
    const uint32_t Abase = smb;           // [2][16384]
    const uint32_t Bbase = smb + 32768;   // [2][16384]
    uint32_t* rmin = (uint32_t*)(sm + 65536);

    const int tid  = threadIdx.x;
    const int lane = tid & 31;
    const int warp = tid >> 5;
    const int bm = blockIdx.x * 128;
    const int bn = blockIdx.y * 128;
    const int wm = (warp & 3) * 32;
    const int wn = (warp >> 2) * 64;

    const char* gA = (const char*)(A16 + (size_t)bm * Dd);
    const char* gB = (const char*)(B16 + (size_t)bn * Dd);

    if (tid < 128) rmin[tid] = 0xFFFFFFFFu;

    uint32_t acc[2][8][2];
    #pragma unroll
    for (int mi = 0; mi < 2; ++mi)
        #pragma unroll
        for (int ni = 0; ni < 8; ++ni) { acc[mi][ni][0] = 0u; acc[mi][ni][1] = 0u; }

    // precomputed fragment row addresses (buf-relative)
    uint32_t arow[2], brow[4];
    #pragma unroll
    for (int mi = 0; mi < 2; ++mi) {
        int row = wm + mi * 16 + (lane & 15);
        arow[mi] = Abase + row * 128 + (((lane >> 4) ^ (row & 7)) * 16);
    }
    #pragma unroll
    for (int nj = 0; nj < 4; ++nj) {
        int row = wn + nj * 16 + (lane & 15);
        brow[nj] = Bbase + row * 128 + (((lane >> 4) ^ (row & 7)) * 16);
    }

    #define LOAD_TILE(kt, buf)                                                  \
        {                                                                       \
            _Pragma("unroll")                                                   \
            for (int i = 0; i < 4; ++i) {                                       \
                int u = tid + 256 * i;                                          \
                int row = u >> 3, ch = u & 7;                                   \
                uint32_t so = (uint32_t)(row * 128 + ((ch ^ (row & 7)) * 16));  \
                size_t go = (size_t)row * (Dd * 2) + (kt) * 128 + ch * 16;      \
                cp16(Abase + (buf) * 16384 + so, gA + go);                      \
                cp16(Bbase + (buf) * 16384 + so, gB + go);                      \
            }                                                                   \
            cp_commit();                                                        \
        }

    #define LOAD_FRAGS(s, boff, areg, breg)                                     \
        {                                                                       \
            const uint32_t sx = (uint32_t)((s) * 2) << 4;                       \
            ldsm4(areg[0], (arow[0] ^ sx) + (boff));                            \
            ldsm4(areg[1], (arow[1] ^ sx) + (boff));                            \
            ldsm4(breg[0], (brow[0] ^ sx) + (boff));                            \
            ldsm4(breg[1], (brow[1] ^ sx) + (boff));                            \
            ldsm4(breg[2], (brow[2] ^ sx) + (boff));                            \
            ldsm4(breg[3], (brow[3] ^ sx) + (boff));                            \
        }

    LOAD_TILE(0, 0);

    uint32_t a[2][2][4], b[2][4][4];

    for (int kt = 0; kt < 8; ++kt) {
        const int buf = kt & 1;
        const uint32_t boff = (uint32_t)buf * 16384;
        cp_wait0();
        __syncthreads();
        if (kt < 7) LOAD_TILE(kt + 1, buf ^ 1);

        LOAD_FRAGS(0, boff, a[0], b[0]);
        #pragma unroll
        for (int s = 0; s < 4; ++s) {
            const int cur = s & 1, nxt = cur ^ 1;
            if (s < 3) LOAD_FRAGS(s + 1, boff, a[nxt], b[nxt]);
            #pragma unroll
            for (int mi = 0; mi < 2; ++mi)
                #pragma unroll
                for (int ni = 0; ni < 8; ++ni)
                    mma_f16acc(acc[mi][ni], a[cur][mi],
                               b[cur][ni >> 1][ni & 1],
                               b[cur][ni >> 1][(ni & 1) + 2]);
        }
    }

    // epilogue: d = c2[n] - 2*acc, fp16 stores + per-token block min
    const int g = lane >> 2, t4 = lane & 3;
    float rm[4] = {3.4e38f, 3.4e38f, 3.4e38f, 3.4e38f};   // [mi*2 + half]
    #pragma unroll
    for (int mi = 0; mi < 2; ++mi) {
        const int m0 = bm + wm + mi * 16 + g;
        #pragma unroll
        for (int ni = 0; ni < 8; ++ni) {
            const int n = bn + wn + ni * 8 + 2 * t4;
            float2 cc = *(const float2*)(c2 + n);
            float2 f0 = __half22float2(*(__half2*)&acc[mi][ni][0]);  // rows m0
            float2 f1 = __half22float2(*(__half2*)&acc[mi][ni][1]);  // rows m0+8
            float d00 = fmaf(-2.0f, f0.x, cc.x), d01 = fmaf(-2.0f, f0.y, cc.y);
            float d10 = fmaf(-2.0f, f1.x, cc.x), d11 = fmaf(-2.0f, f1.y, cc.y);
            rm[mi * 2]     = fminf(rm[mi * 2],     fminf(d00, d01));
            rm[mi * 2 + 1] = fminf(rm[mi * 2 + 1], fminf(d10, d11));
            *(__half2*)(dist + (size_t)m0 * Kk + n)       = __floats2half2_rn(d00, d01);
            *(__half2*)(dist + (size_t)(m0 + 8) * Kk + n) = __floats2half2_rn(d10, d11);
        }
    }
    #pragma unroll
    for (int h = 0; h < 4; ++h) {
        int row = wm + (h >> 1) * 16 + g + (h & 1) * 8;   // local token row
        atomicMin(&rmin[row], ordkey(rm[h]));
    }
    __syncthreads();
    if (tid < 128)
        bminO[(size_t)blockIdx.y * Mm + bm + tid] = orddec(rmin[tid]);
    #undef LOAD_TILE
    #undef LOAD_FRAGS
}

// ---------------------------------------------------------------------------
// Fused refine + update: warp per token, gated by per-block minima.
// gmin over 8 block mins -> thresh; only blocks with bmin <= thresh have
// their 128 dists read. Exact fp32 rescore + residual/res16/loss/index
// update (residual held in registers).
// ---------------------------------------------------------------------------
__global__ __launch_bounds__(256)
void refine_update_kernel(const __half* __restrict__ dist,
                          const float* __restrict__ bminI,
                          float* __restrict__ R,
                          __half* __restrict__ R16w,
                          const float* __restrict__ C,
                          const float* __restrict__ c2,
                          float* __restrict__ out_idx,
                          float* __restrict__ loss,
                          int qstage)
{
    const int warp = threadIdx.x >> 5, lane = threadIdx.x & 31;
    const int token = blockIdx.x * 8 + warp;

    float bm_l = 3.4e38f;
    if (lane < 8) bm_l = bminI[(size_t)lane * Mm + token];
    float gmin = bm_l;
    #pragma unroll
    for (int o = 16; o; o >>= 1) gmin = fminf(gmin, __shfl_xor_sync(~0u, gmin, o));
    const float thresh = gmin + MARGIN;

    unsigned qb = __ballot_sync(~0u, bm_l <= thresh);   // lanes>=8 have +inf

    // residual in registers (used by rescore AND update)
    const float4* rrp = (const float4*)(R + (size_t)token * Dd);
    float4 rr[4];
    #pragma unroll
    for (int j = 0; j < 4; ++j) rr[j] = rrp[lane + 32 * j];

    float bd = 3.4e38f;
    int   bn = 1 << 30;

    while (qb) {
        const int blk = __ffs(qb) - 1;
        qb &= qb - 1;

        // load this block's 128 dists: 4 halves per lane
        uint2 u = *(const uint2*)(dist + (size_t)token * Kk + blk * 128 + lane * 4);
        float2 fa = __half22float2(*(__half2*)&u.x);
        float2 fb = __half22float2(*(__half2*)&u.y);
        float f[4] = {fa.x, fa.y, fb.x, fb.y};
        unsigned m4 = 0;
        #pragma unroll
        for (int j = 0; j < 4; ++j)
            if (f[j] <= thresh) m4 |= 1u << j;

        while (true) {
            unsigned has = __ballot_sync(~0u, m4 != 0);
            if (!has) break;
            int leader = __ffs(has) - 1;
            int j = 0;
            if (lane == leader) { j = __ffs(m4) - 1; m4 &= m4 - 1; }
            j = __shfl_sync(~0u, j, leader);
            const int n = blk * 128 + 4 * leader + j;

            const float4* cc4 = (const float4*)(C + (size_t)n * Dd);
            float ssum = 0.0f;
            #pragma unroll
            for (int t = 0; t < 4; ++t) {
                float4 b = cc4[lane + 32 * t];
                ssum += rr[t].x * b.x + rr[t].y * b.y +
                        rr[t].z * b.z + rr[t].w * b.w;
            }
            #pragma unroll
            for (int o = 16; o; o >>= 1) ssum += __shfl_xor_sync(~0u, ssum, o);

            float d = fmaf(-2.0f, ssum, __ldg(c2 + n));
            if (d < bd || (d == bd && n < bn)) { bd = d; bn = n; }
        }
    }

    // fused update (residual already in rr)
    const float4* cp = (const float4*)(C + (size_t)bn * Dd);
    float4* rp = (float4*)(R + (size_t)token * Dd);
    __half2* r16p = (__half2*)(R16w + (size_t)token * Dd);
    float lsum = 0.0f;
    #pragma unroll
    for (int j = 0; j < 4; ++j) {
        float4 cv = cp[lane + 32 * j];
        float4 nr = make_float4(rr[j].x - cv.x, rr[j].y - cv.y,
                                rr[j].z - cv.z, rr[j].w - cv.w);
        rp[lane + 32 * j] = nr;
        r16p[2 * (lane + 32 * j)]     = __floats2half2_rn(nr.x, nr.y);
        r16p[2 * (lane + 32 * j) + 1] = __floats2half2_rn(nr.z, nr.w);
        lsum += nr.x * nr.x + nr.y * nr.y + nr.z * nr.z + nr.w * nr.w;
    }
    #pragma unroll
    for (int o = 16; o; o >>= 1) lsum += __shfl_xor_sync(~0u, lsum, o);
    if (lane == 0) {
        out_idx[(size_t)token * Qq + qstage] = (float)bn;
        atomicAdd(loss, lsum);
    }
}

// ---------------------------------------------------------------------------
// Final: quantized_out = x - residual_final  (one pass)
// ---------------------------------------------------------------------------
__global__ void final_out_kernel(const float4* __restrict__ x,
                                 const float4* __restrict__ residual,
                                 float4* __restrict__ out, int n4)
{
    int i = blockIdx.x * 256 + threadIdx.x;
    if (i < n4) {
        float4 a = x[i], r = residual[i];
        out[i] = make_float4(a.x - r.x, a.y - r.y, a.z - r.z, a.w - r.w);
    }
}

// Tail outputs: all_expired (zeros) then all_losses (mean over B*S*D)
__global__ void finalize_kernel(float* __restrict__ out, const float* __restrict__ loss)
{
    const size_t base = (size_t)Mm * Dd + (size_t)Mm * Qq;
    int t = threadIdx.x;
    if (t < Qq)
        out[base + t] = 0.0f;
    else if (t < 2 * Qq)
        out[base + Qq + (t - Qq)] = loss[t - Qq] * (1.0f / ((float)Mm * (float)Dd));
}

// ---------------------------------------------------------------------------
extern "C" void kernel_launch(void* const* d_in, const int* in_sizes, int n_in,
                              void* d_out, int out_size)
{
    const float* x  = (const float*)d_in[0];   // [B,S,D] f32
    const float* cb = (const float*)d_in[1];   // [Q,K,D] f32
    float* out = (float*)d_out;

    float* residual;   cudaGetSymbolAddress((void**)&residual, g_residual);
    __half* res16;     cudaGetSymbolAddress((void**)&res16,    g_res16);
    __half* cb16;      cudaGetSymbolAddress((void**)&cb16,     g_cb16);
    __half* dist;      cudaGetSymbolAddress((void**)&dist,     g_dist);
    float* bmin;       cudaGetSymbolAddress((void**)&bmin,     g_bmin);
    float* c2;         cudaGetSymbolAddress((void**)&c2,       g_c2);
    float* loss;       cudaGetSymbolAddress((void**)&loss,     g_loss);

    cudaFuncSetAttribute(gemm_dist_kernel,
                         cudaFuncAttributeMaxDynamicSharedMemorySize, GEMM_SMEM);

    cudaMemsetAsync(loss, 0, Qq * sizeof(float));

    init_kernel<<<Mm * Dd / 4 / 256, 256>>>((const float4*)x, (float4*)residual,
                                            (__half2*)res16, Mm * Dd / 4);
    conv_kernel<<<(Qq * Kk * Dd / 4 + 255) / 256, 256>>>((const float4*)cb,
                                                         (__half2*)cb16,
                                                         Qq * Kk * Dd / 4);
    c2_kernel<<<Qq * Kk / 8, 256>>>(cb, c2);

    for (int q = 0; q < Qq; ++q) {
        const float* Cq = cb + (size_t)q * Kk * Dd;
        const __half* Cq16 = cb16 + (size_t)q * Kk * Dd;
        dim3 grid(Mm / 128, Kk / 128);
        gemm_dist_kernel<<<grid, 256, GEMM_SMEM>>>(res16, Cq16, c2 + q * Kk,
                                                   dist, bmin);
        refine_update_kernel<<<Mm / 8, 256>>>(dist, bmin, residual, res16, Cq,
                                              c2 + q * Kk,
                                              out + (size_t)Mm * Dd, loss + q, q);
    }

    final_out_kernel<<<Mm * Dd / 4 / 256, 256>>>((const float4*)x,
                                                 (const float4*)residual,
                                                 (float4*)out, Mm * Dd / 4);
    finalize_kernel<<<1, 2 * Qq>>>(out, loss);
}

// round 14
// speedup vs baseline: 1.1503x; 1.1503x over previous
#include <cuda_runtime.h>
#include <cuda_fp16.h>
#include <cstdint>

// Problem constants
#define Bb 8
#define Ss 2048
#define Dd 512
#define Qq 8
#define Kk 1024
#define Mm (Bb * Ss)   // 16384 tokens
#define HALF_M (Mm / 2)
#define MARGIN 8.0f

// Scratch (no cudaMalloc allowed)
__device__ float   g_residual[Mm * Dd];   // 32 MB fp32 residual
__device__ __half  g_res16[Mm * Dd];      // 16 MB fp16 residual
__device__ __half  g_cb16[Qq * Kk * Dd];  //  8 MB fp16 codebooks
__device__ __half  g_dist[Mm * Kk];       // 32 MB approx distances (fp16)
__device__ float   g_c2[Qq * Kk];
__device__ float   g_loss[Qq];

// ---------------------------------------------------------------------------
// helpers
// ---------------------------------------------------------------------------
__device__ __forceinline__ uint32_t smem_u32(const void* p) {
    uint32_t a;
    asm("{ .reg .u64 t; cvta.to.shared.u64 t, %1; cvt.u32.u64 %0, t; }"
        : "=r"(a) : "l"(p));
    return a;
}
__device__ __forceinline__ void cp16(uint32_t sa, const void* g) {
    asm volatile("cp.async.cg.shared.global [%0], [%1], 16;"
                 :: "r"(sa), "l"(g) : "memory");
}
__device__ __forceinline__ void cp_commit() {
    asm volatile("cp.async.commit_group;" ::: "memory");
}
__device__ __forceinline__ void cp_wait0() {
    asm volatile("cp.async.wait_group 0;" ::: "memory");
}
__device__ __forceinline__ void ldsm4(uint32_t* r, uint32_t addr) {
    asm volatile("ldmatrix.sync.aligned.m8n8.x4.shared.b16 {%0,%1,%2,%3}, [%4];"
                 : "=r"(r[0]), "=r"(r[1]), "=r"(r[2]), "=r"(r[3])
                 : "r"(addr));
}
// fp16 inputs, fp16 accumulators (2 x b32 regs hold 4 halves)
__device__ __forceinline__ void mma_f16acc(uint32_t* c, const uint32_t* a,
                                           uint32_t b0, uint32_t b1) {
    asm volatile(
        "mma.sync.aligned.m16n8k16.row.col.f16.f16.f16.f16 "
        "{%0,%1}, {%2,%3,%4,%5}, {%6,%7}, {%0,%1};"
        : "+r"(c[0]), "+r"(c[1])
        : "r"(a[0]), "r"(a[1]), "r"(a[2]), "r"(a[3]), "r"(b0), "r"(b1));
}

// ---------------------------------------------------------------------------
// init: residual=x (fp32), res16=fp16(x)
// ---------------------------------------------------------------------------
__global__ void init_kernel(const float4* __restrict__ x,
                            float4* __restrict__ residual,
                            __half2* __restrict__ res16, int n4)
{
    int i = blockIdx.x * 256 + threadIdx.x;
    if (i < n4) {
        float4 v = x[i];
        residual[i] = v;
        res16[2 * i]     = __floats2half2_rn(v.x, v.y);
        res16[2 * i + 1] = __floats2half2_rn(v.z, v.w);
    }
}

// fp32 -> fp16 codebook convert
__global__ void conv_kernel(const float4* __restrict__ in,
                            __half2* __restrict__ out, int n4)
{
    int i = blockIdx.x * 256 + threadIdx.x;
    if (i < n4) {
        float4 v = in[i];
        out[2 * i]     = __floats2half2_rn(v.x, v.y);
        out[2 * i + 1] = __floats2half2_rn(v.z, v.w);
    }
}

// ---------------------------------------------------------------------------
// c2[q][k] = ||codebook[q][k]||^2  — one warp per row (fp32 exact)
// ---------------------------------------------------------------------------
__global__ void c2_kernel(const float* __restrict__ codebooks, float* __restrict__ c2)
{
    int row  = blockIdx.x * 8 + (threadIdx.x >> 5);
    int lane = threadIdx.x & 31;
    const float4* p = (const float4*)(codebooks + (size_t)row * Dd);
    float s = 0.0f;
    #pragma unroll 4
    for (int i = lane; i < Dd / 4; i += 32) {
        float4 v = p[i];
        s += v.x * v.x + v.y * v.y + v.z * v.z + v.w * v.w;
    }
    #pragma unroll
    for (int off = 16; off; off >>= 1) s += __shfl_down_sync(0xffffffffu, s, off);
    if (lane == 0) c2[row] = s;
}

// ---------------------------------------------------------------------------
// fp16 mma.sync GEMM (fp16 acc) -> approx distances (fp16 stores).
// CTA 128x128, BK=64, 8 warps of 32x64, double-buffered cp.async, one sync
// per k-tile, fragment loads software-pipelined across the s-loop.
// (operates on a token-half: A16/dist pointers pre-offset by the caller)
// ---------------------------------------------------------------------------
#define GEMM_SMEM 65536   // 2 bufs * (A 16KB + B 16KB)

__global__ __launch_bounds__(256, 2)
void gemm_dist_kernel(const __half* __restrict__ A16,
                      const __half* __restrict__ B16,
                      const float* __restrict__ c2,
                      __half* __restrict__ dist)
{
    extern __shared__ char sm[];
    const uint32_t smb   = smem_u32(sm);
    const uint32_t Abase = smb;           // [2][16384]
    const uint32_t Bbase = smb + 32768;   // [2][16384]

    const int tid  = threadIdx.x;
    const int lane = tid & 31;
    const int warp = tid >> 5;
    const int bm = blockIdx.x * 128;
    const int bn = blockIdx.y * 128;
    const int wm = (warp & 3) * 32;
    const int wn = (warp >> 2) * 64;

    const char* gA = (const char*)(A16 + (size_t)bm * Dd);
    const char* gB = (const char*)(B16 + (size_t)bn * Dd);

    uint32_t acc[2][8][2];
    #pragma unroll
    for (int mi = 0; mi < 2; ++mi)
        #pragma unroll
        for (int ni = 0; ni < 8; ++ni) { acc[mi][ni][0] = 0u; acc[mi][ni][1] = 0u; }

    // precomputed fragment row addresses (buf-relative)
    uint32_t arow[2], brow[4];
    #pragma unroll
    for (int mi = 0; mi < 2; ++mi) {
        int row = wm + mi * 16 + (lane & 15);
        arow[mi] = Abase + row * 128 + (((lane >> 4) ^ (row & 7)) * 16);
    }
    #pragma unroll
    for (int nj = 0; nj < 4; ++nj) {
        int row = wn + nj * 16 + (lane & 15);
        brow[nj] = Bbase + row * 128 + (((lane >> 4) ^ (row & 7)) * 16);
    }

    #define LOAD_TILE(kt, buf)                                                  \
        {                                                                       \
            _Pragma("unroll")                                                   \
            for (int i = 0; i < 4; ++i) {                                       \
                int u = tid + 256 * i;                                          \
                int row = u >> 3, ch = u & 7;                                   \
                uint32_t so = (uint32_t)(row * 128 + ((ch ^ (row & 7)) * 16));  \
                size_t go = (size_t)row * (Dd * 2) + (kt) * 128 + ch * 16;      \
                cp16(Abase + (buf) * 16384 + so, gA + go);                      \
                cp16(Bbase + (buf) * 16384 + so, gB + go);                      \
            }                                                                   \
            cp_commit();                                                        \
        }

    #define LOAD_FRAGS(s, boff, areg, breg)                                     \
        {                                                                       \
            const uint32_t sx = (uint32_t)((s) * 2) << 4;                       \
            ldsm4(areg[0], (arow[0] ^ sx) + (boff));                            \
            ldsm4(areg[1], (arow[1] ^ sx) + (boff));                            \
            ldsm4(breg[0], (brow[0] ^ sx) + (boff));                            \
            ldsm4(breg[1], (brow[1] ^ sx) + (boff));                            \
            ldsm4(breg[2], (brow[2] ^ sx) + (boff));                            \
            ldsm4(breg[3], (brow[3] ^ sx) + (boff));                            \
        }

    LOAD_TILE(0, 0);

    uint32_t a[2][2][4], b[2][4][4];

    for (int kt = 0; kt < 8; ++kt) {
        const int buf = kt & 1;
        const uint32_t boff = (uint32_t)buf * 16384;
        cp_wait0();
        __syncthreads();
        if (kt < 7) LOAD_TILE(kt + 1, buf ^ 1);

        LOAD_FRAGS(0, boff, a[0], b[0]);
        #pragma unroll
        for (int s = 0; s < 4; ++s) {
            const int cur = s & 1, nxt = cur ^ 1;
            if (s < 3) LOAD_FRAGS(s + 1, boff, a[nxt], b[nxt]);
            #pragma unroll
            for (int mi = 0; mi < 2; ++mi)
                #pragma unroll
                for (int ni = 0; ni < 8; ++ni)
                    mma_f16acc(acc[mi][ni], a[cur][mi],
                               b[cur][ni >> 1][ni & 1],
                               b[cur][ni >> 1][(ni & 1) + 2]);
        }
    }

    // epilogue: d = c2[n] - 2*acc (acc fp16 -> fp32), fp16 stores
    const int g = lane >> 2, t4 = lane & 3;
    #pragma unroll
    for (int mi = 0; mi < 2; ++mi) {
        const int m0 = bm + wm + mi * 16 + g;
        #pragma unroll
        for (int ni = 0; ni < 8; ++ni) {
            const int n = bn + wn + ni * 8 + 2 * t4;
            float2 cc = *(const float2*)(c2 + n);
            float2 f0 = __half22float2(*(__half2*)&acc[mi][ni][0]);  // rows m0
            float2 f1 = __half22float2(*(__half2*)&acc[mi][ni][1]);  // rows m0+8
            __half2 h0 = __floats2half2_rn(fmaf(-2.0f, f0.x, cc.x),
                                           fmaf(-2.0f, f0.y, cc.y));
            __half2 h1 = __floats2half2_rn(fmaf(-2.0f, f1.x, cc.x),
                                           fmaf(-2.0f, f1.y, cc.y));
            *(__half2*)(dist + (size_t)m0 * Kk + n)       = h0;
            *(__half2*)(dist + (size_t)(m0 + 8) * Kk + n) = h1;
        }
    }
    #undef LOAD_TILE
    #undef LOAD_FRAGS
}

// ---------------------------------------------------------------------------
// Fused refine + update: warp per token (pointers pre-offset to token half).
// ---------------------------------------------------------------------------
__global__ __launch_bounds__(256)
void refine_update_kernel(const __half* __restrict__ dist,
                          float* __restrict__ R,
                          __half* __restrict__ R16w,
                          const float* __restrict__ C,
                          const float* __restrict__ c2,
                          float* __restrict__ out_idx,
                          float* __restrict__ loss,
                          int qstage)
{
    const int warp = threadIdx.x >> 5, lane = threadIdx.x & 31;
    const int token = blockIdx.x * 8 + warp;

    // scan fp16 distances: 4 x uint4 per lane = 32 halves
    const uint4* dp = (const uint4*)(dist + (size_t)token * Kk);
    float v[32];
    float vmin = 3.4e38f;
    #pragma unroll
    for (int i = 0; i < 4; ++i) {
        uint4 u = dp[lane + 32 * i];
        const __half2* hp = (const __half2*)&u;
        #pragma unroll
        for (int p = 0; p < 4; ++p) {
            float2 f = __half22float2(hp[p]);
            v[8 * i + 2 * p]     = f.x;
            v[8 * i + 2 * p + 1] = f.y;
            vmin = fminf(vmin, fminf(f.x, f.y));
        }
    }
    #pragma unroll
    for (int o = 16; o; o >>= 1) vmin = fminf(vmin, __shfl_xor_sync(~0u, vmin, o));

    const float thresh = vmin + MARGIN;
    unsigned mask = 0;
    #pragma unroll
    for (int s = 0; s < 32; ++s)
        if (v[s] <= thresh) mask |= 1u << s;

    // residual in registers (used by rescore AND update)
    const float4* rrp = (const float4*)(R + (size_t)token * Dd);
    float4 rr[4];
    #pragma unroll
    for (int j = 0; j < 4; ++j) rr[j] = rrp[lane + 32 * j];

    float bd = 3.4e38f;
    int   bn = 1 << 30;

    while (true) {
        unsigned has = __ballot_sync(~0u, mask != 0);
        if (!has) break;
        int leader = __ffs(has) - 1;
        int s = 0;
        if (lane == leader) { s = __ffs(mask) - 1; mask &= mask - 1; }
        s = __shfl_sync(~0u, s, leader);
        // value v[s] of lane `leader` is code n = 8*(leader + 32*(s>>3)) + (s&7)
        const int n = 8 * (leader + 32 * (s >> 3)) + (s & 7);

        const float4* cc4 = (const float4*)(C + (size_t)n * Dd);
        float ssum = 0.0f;
        #pragma unroll
        for (int t = 0; t < 4; ++t) {
            float4 b = cc4[lane + 32 * t];
            ssum += rr[t].x * b.x + rr[t].y * b.y + rr[t].z * b.z + rr[t].w * b.w;
        }
        #pragma unroll
        for (int o = 16; o; o >>= 1) ssum += __shfl_xor_sync(~0u, ssum, o);

        float d = fmaf(-2.0f, ssum, __ldg(c2 + n));
        if (d < bd || (d == bd && n < bn)) { bd = d; bn = n; }
    }

    // fused update (residual already in rr)
    const float4* cp = (const float4*)(C + (size_t)bn * Dd);
    float4* rp = (float4*)(R + (size_t)token * Dd);
    __half2* r16p = (__half2*)(R16w + (size_t)token * Dd);
    float lsum = 0.0f;
    #pragma unroll
    for (int j = 0; j < 4; ++j) {
        float4 cv = cp[lane + 32 * j];
        float4 nr = make_float4(rr[j].x - cv.x, rr[j].y - cv.y,
                                rr[j].z - cv.z, rr[j].w - cv.w);
        rp[lane + 32 * j] = nr;
        r16p[2 * (lane + 32 * j)]     = __floats2half2_rn(nr.x, nr.y);
        r16p[2 * (lane + 32 * j) + 1] = __floats2half2_rn(nr.z, nr.w);
        lsum += nr.x * nr.x + nr.y * nr.y + nr.z * nr.z + nr.w * nr.w;
    }
    #pragma unroll
    for (int o = 16; o; o >>= 1) lsum += __shfl_xor_sync(~0u, lsum, o);
    if (lane == 0) {
        out_idx[(size_t)token * Qq + qstage] = (float)bn;
        atomicAdd(loss, lsum);
    }
}

// ---------------------------------------------------------------------------
// Final: quantized_out = x - residual_final  (one pass)
// ---------------------------------------------------------------------------
__global__ void final_out_kernel(const float4* __restrict__ x,
                                 const float4* __restrict__ residual,
                                 float4* __restrict__ out, int n4)
{
    int i = blockIdx.x * 256 + threadIdx.x;
    if (i < n4) {
        float4 a = x[i], r = residual[i];
        out[i] = make_float4(a.x - r.x, a.y - r.y, a.z - r.z, a.w - r.w);
    }
}

// Tail outputs: all_expired (zeros) then all_losses (mean over B*S*D)
__global__ void finalize_kernel(float* __restrict__ out, const float* __restrict__ loss)
{
    const size_t base = (size_t)Mm * Dd + (size_t)Mm * Qq;
    int t = threadIdx.x;
    if (t < Qq)
        out[base + t] = 0.0f;
    else if (t < 2 * Qq)
        out[base + Qq + (t - Qq)] = loss[t - Qq] * (1.0f / ((float)Mm * (float)Dd));
}

// ---------------------------------------------------------------------------
extern "C" void kernel_launch(void* const* d_in, const int* in_sizes, int n_in,
                              void* d_out, int out_size)
{
    const float* x  = (const float*)d_in[0];   // [B,S,D] f32
    const float* cb = (const float*)d_in[1];   // [Q,K,D] f32
    float* out = (float*)d_out;

    float* residual;   cudaGetSymbolAddress((void**)&residual, g_residual);
    __half* res16;     cudaGetSymbolAddress((void**)&res16,    g_res16);
    __half* cb16;      cudaGetSymbolAddress((void**)&cb16,     g_cb16);
    __half* dist;      cudaGetSymbolAddress((void**)&dist,     g_dist);
    float* c2;         cudaGetSymbolAddress((void**)&c2,       g_c2);
    float* loss;       cudaGetSymbolAddress((void**)&loss,     g_loss);

    // one-time resources (created on the first, uncaptured, correctness call)
    static cudaStream_t s2 = nullptr;
    static cudaEvent_t  evF = nullptr, evJ = nullptr;
    if (!s2) {
        cudaStreamCreateWithFlags(&s2, cudaStreamNonBlocking);
        cudaEventCreateWithFlags(&evF, cudaEventDisableTiming);
        cudaEventCreateWithFlags(&evJ, cudaEventDisableTiming);
        cudaFuncSetAttribute(gemm_dist_kernel,
                             cudaFuncAttributeMaxDynamicSharedMemorySize,
                             GEMM_SMEM);
    }

    // shared setup on the capture (default) stream
    cudaMemsetAsync(loss, 0, Qq * sizeof(float));
    init_kernel<<<Mm * Dd / 4 / 256, 256>>>((const float4*)x, (float4*)residual,
                                            (__half2*)res16, Mm * Dd / 4);
    conv_kernel<<<(Qq * Kk * Dd / 4 + 255) / 256, 256>>>((const float4*)cb,
                                                         (__half2*)cb16,
                                                         Qq * Kk * Dd / 4);
    c2_kernel<<<Qq * Kk / 8, 256>>>(cb, c2);

    // fork: half H1 chain runs on s2
    cudaEventRecord(evF, 0);
    cudaStreamWaitEvent(s2, evF, 0);

    const size_t offE = (size_t)HALF_M * Dd;   // element offset of half 1
    float* out_idx = out + (size_t)Mm * Dd;

    for (int q = 0; q < Qq; ++q) {
        const float* Cq = cb + (size_t)q * Kk * Dd;
        const __half* Cq16 = cb16 + (size_t)q * Kk * Dd;
        dim3 grid(HALF_M / 128, Kk / 128);

        // half 0 on default stream
        gemm_dist_kernel<<<grid, 256, GEMM_SMEM, 0>>>(
            res16, Cq16, c2 + q * Kk, dist);
        refine_update_kernel<<<HALF_M / 8, 256, 0, 0>>>(
            dist, residual, res16, Cq, c2 + q * Kk, out_idx, loss + q, q);

        // half 1 on s2
        gemm_dist_kernel<<<grid, 256, GEMM_SMEM, s2>>>(
            res16 + offE, Cq16, c2 + q * Kk, dist + (size_t)HALF_M * Kk);
        refine_update_kernel<<<HALF_M / 8, 256, 0, s2>>>(
            dist + (size_t)HALF_M * Kk, residual + offE, res16 + offE,
            Cq, c2 + q * Kk, out_idx + (size_t)HALF_M * Qq, loss + q, q);
    }

    // join
    cudaEventRecord(evJ, s2);
    cudaStreamWaitEvent(0, evJ, 0);

    final_out_kernel<<<Mm * Dd / 4 / 256, 256>>>((const float4*)x,
                                                 (const float4*)residual,
                                                 (float4*)out, Mm * Dd / 4);
    finalize_kernel<<<1, 2 * Qq>>>(out, loss);
}